// round 7
// baseline (speedup 1.0000x reference)
#include <cuda_runtime.h>
#include <cstdint>

#define EMB 512
#define BATCH 8
#define SEQ 2048
#define TOK (BATCH * SEQ)   // 16384

// Scratch (allocation-free rule: __device__ globals)
__device__ float g_X[(size_t)TOK * EMB];
__device__ float g_QKV[(size_t)TOK * 3 * EMB];
__device__ float g_Vt[(size_t)TOK * EMB];
__device__ float g_O[(size_t)TOK * EMB];
__device__ float g_S[(size_t)BATCH * SEQ * SEQ];
__device__ float g_WT[4 * EMB * EMB];
__device__ float g_Bqkv[3 * EMB];
__device__ float g_Lpart[32 * TOK];
__device__ float g_L[TOK];

// ---------------- PTX helpers (compute_103-safe) ----------------
__device__ __forceinline__ uint32_t smem_u32(const void* p) {
    uint32_t a;
    asm("{ .reg .u64 t; cvta.to.shared.u64 t, %1; cvt.u32.u64 %0, t; }" : "=r"(a) : "l"(p));
    return a;
}
__device__ __forceinline__ void cp16(uint32_t s, const void* g) {
    asm volatile("cp.async.cg.shared.global [%0], [%1], 16;" :: "r"(s), "l"(g));
}
#define CP_COMMIT() asm volatile("cp.async.commit_group;" ::: "memory")
#define CP_WAIT(n)  asm volatile("cp.async.wait_group %0;" :: "n"(n) : "memory")

__device__ __forceinline__ float f2tf32f(float x) {
    unsigned u; asm("cvt.rna.tf32.f32 %0, %1;" : "=r"(u) : "f"(x));
    return __uint_as_float(u);
}

// FMA-pipe exp (no MUFU): x ~ [-16,16], rel err ~2e-6.
__device__ __forceinline__ float fexp(float x) {
    float t = x * 1.4426950408889634f;
    float r = rintf(t);
    float f = t - r;
    float p =          1.3333558146428443e-3f;
    p = fmaf(p, f,     9.6181291076284772e-3f);
    p = fmaf(p, f,     5.5504108664821580e-2f);
    p = fmaf(p, f,     2.4022650695910071e-1f);
    p = fmaf(p, f,     6.9314718055994531e-1f);
    p = fmaf(p, f,     1.0f);
    int i = (int)r;
    return p * __int_as_float((i + 127) << 23);
}

__device__ __forceinline__ void mma_tf32(float* d, const float2 a01, const float2 a23,
                                         const float2 b01) {
    asm volatile(
        "mma.sync.aligned.m16n8k8.row.col.f32.tf32.tf32.f32 "
        "{%0,%1,%2,%3}, {%4,%5,%6,%7}, {%8,%9}, {%0,%1,%2,%3};"
        : "+f"(d[0]), "+f"(d[1]), "+f"(d[2]), "+f"(d[3])
        : "r"(__float_as_uint(a01.x)), "r"(__float_as_uint(a23.x)),
          "r"(__float_as_uint(a01.y)), "r"(__float_as_uint(a23.y)),
          "r"(__float_as_uint(b01.x)), "r"(__float_as_uint(b01.y)));
}

// ---------------- NT tf32 GEMM ----------------
// C = scale * A @ B^T (+epilogue). Pre-rounded tf32 operands. Block tile
// 128x128, BK=32, 4 warps (2x2), warp tile 64x64, 2-stage cp.async pipeline
// (2 CTAs/SM), stride-40 smem. Fragment k-pair remapped to (2q,2q+1) — a
// permutation of k applied to BOTH operands (GEMM-invariant) — so every
// fragment load is one conflict-free ld.shared.v2.
// EPI: 0 = +bias, round (QKV proj)   1 = exp, row-partial-sums, round (score)
//      2 = *invl[row], round (AV)    3 = +bias (final)
#define BK 32
#define STRIDE 40
#define TILE_FLOATS (128 * STRIDE)           // 5120
#define STAGE_FLOATS (2 * TILE_FLOATS)       // 10240
#define SMEM_BYTES (2 * STAGE_FLOATS * 4)    // 81920

template <int EPI>
__global__ void __launch_bounds__(128, 2) gemm_nt(
    const float* __restrict__ A, const float* __restrict__ B,
    const float* __restrict__ aux, float* __restrict__ C,
    int lda, int ldb, int ldc, int K,
    size_t sA, size_t sB, size_t sC, int sAux, float scale)
{
    extern __shared__ float smem[];
    const uint32_t sbase = smem_u32(smem);

    const int tid  = threadIdx.x;
    const int lane = tid & 31;
    const int warp = tid >> 5;
    const int wr = (warp & 1) * 64;
    const int wc = (warp >> 1) * 64;

    const int b = blockIdx.z;
    A += (size_t)b * sA;
    B += (size_t)b * sB;
    C += (size_t)b * sC;
    if (aux) aux += (size_t)b * sAux;
    const int row0 = blockIdx.y * 128;
    const int col0 = blockIdx.x * 128;

    float acc[4][8][4];
    #pragma unroll
    for (int mi = 0; mi < 4; mi++)
        #pragma unroll
        for (int ni = 0; ni < 8; ni++)
            #pragma unroll
            for (int j = 0; j < 4; j++) acc[mi][ni][j] = 0.0f;

    const float* gA = A + (size_t)row0 * lda;
    const float* gB = B + (size_t)col0 * ldb;
    const int frow0 = tid >> 3;
    const int fkq   = tid & 7;

    auto fill = [&](int t, int buf) {
        uint32_t smA = sbase + (uint32_t)buf * STAGE_FLOATS * 4;
        uint32_t smB = smA + TILE_FLOATS * 4;
        const float* pa = gA + t * BK + fkq * 4;
        const float* pb = gB + t * BK + fkq * 4;
        int row = frow0;
        #pragma unroll
        for (int it = 0; it < 8; it++, row += 16) {
            uint32_t off = (uint32_t)(row * STRIDE + fkq * 4) * 4;
            cp16(smA + off, pa + (size_t)row * lda);
            cp16(smB + off, pb + (size_t)row * ldb);
        }
    };

    const int ktiles = K / BK;
    fill(0, 0); CP_COMMIT();

    const int g = lane >> 2;
    const int q = lane & 3;

    for (int t = 0; t < ktiles; t++) {
        if (t + 1 < ktiles) fill(t + 1, (t + 1) & 1);
        CP_COMMIT();            // possibly empty group (keeps WAIT(1) exact)
        CP_WAIT(1);             // fill(t) resident
        __syncthreads();

        const float* sA_ = smem + (t & 1) * STAGE_FLOATS;
        const float* sB_ = sA_ + TILE_FLOATS;

        #pragma unroll
        for (int ks = 0; ks < 4; ks++) {
            const int kb = ks * 8 + 2 * q;   // k-pair (2q, 2q+1), same perm on A & B
            float2 a01[4], a23[4];
            #pragma unroll
            for (int mi = 0; mi < 4; mi++) {
                int r = wr + mi * 16 + g;
                a01[mi] = *reinterpret_cast<const float2*>(&sA_[r * STRIDE + kb]);
                a23[mi] = *reinterpret_cast<const float2*>(&sA_[(r + 8) * STRIDE + kb]);
            }
            #pragma unroll
            for (int ni = 0; ni < 8; ni++) {
                int n = wc + ni * 8 + g;
                float2 b01 = *reinterpret_cast<const float2*>(&sB_[n * STRIDE + kb]);
                #pragma unroll
                for (int mi = 0; mi < 4; mi++)
                    mma_tf32(acc[mi][ni], a01[mi], a23[mi], b01);
            }
        }
        __syncthreads();        // buf (t&1) free before refill at t+2
    }

    // Epilogue
    float rs0[4], rs1[4];
    #pragma unroll
    for (int mi = 0; mi < 4; mi++) { rs0[mi] = 0.0f; rs1[mi] = 0.0f; }

    #pragma unroll
    for (int mi = 0; mi < 4; mi++) {
        int rloc = wr + mi * 16 + g;
        int r = row0 + rloc;
        float il0 = 1.0f, il1 = 1.0f;
        if (EPI == 2) { il0 = aux[r]; il1 = aux[r + 8]; }
        float* c0 = C + (size_t)r * ldc + col0;
        float* c1 = c0 + (size_t)8 * ldc;
        #pragma unroll
        for (int ni = 0; ni < 8; ni++) {
            int c = wc + ni * 8 + 2 * q;
            float2 v0, v1;
            v0.x = acc[mi][ni][0] * scale;
            v0.y = acc[mi][ni][1] * scale;
            v1.x = acc[mi][ni][2] * scale;
            v1.y = acc[mi][ni][3] * scale;
            if (EPI == 0 || EPI == 3) {
                float bx = aux[col0 + c], by = aux[col0 + c + 1];
                v0.x += bx; v0.y += by;
                v1.x += bx; v1.y += by;
            }
            if (EPI == 1) {
                v0.x = fexp(v0.x); v0.y = fexp(v0.y);
                v1.x = fexp(v1.x); v1.y = fexp(v1.y);
                rs0[mi] += v0.x + v0.y;
                rs1[mi] += v1.x + v1.y;
            }
            if (EPI == 2) {
                v0.x *= il0; v0.y *= il0;
                v1.x *= il1; v1.y *= il1;
            }
            if (EPI != 3) {
                v0.x = f2tf32f(v0.x); v0.y = f2tf32f(v0.y);
                v1.x = f2tf32f(v1.x); v1.y = f2tf32f(v1.y);
            }
            *reinterpret_cast<float2*>(c0 + c) = v0;
            *reinterpret_cast<float2*>(c1 + c) = v1;
        }
    }

    if (EPI == 1) {
        // reduce partial row sums across q (4 lanes per row), write Lpart
        #pragma unroll
        for (int mi = 0; mi < 4; mi++) {
            rs0[mi] += __shfl_xor_sync(0xFFFFFFFF, rs0[mi], 1);
            rs0[mi] += __shfl_xor_sync(0xFFFFFFFF, rs0[mi], 2);
            rs1[mi] += __shfl_xor_sync(0xFFFFFFFF, rs1[mi], 1);
            rs1[mi] += __shfl_xor_sync(0xFFFFFFFF, rs1[mi], 2);
        }
        if (q == 0) {
            int slot = blockIdx.x * 2 + (warp >> 1);
            size_t base = (size_t)slot * TOK + (size_t)b * SEQ + row0 + wr;
            #pragma unroll
            for (int mi = 0; mi < 4; mi++) {
                g_Lpart[base + mi * 16 + g]     = rs0[mi];
                g_Lpart[base + mi * 16 + g + 8] = rs1[mi];
            }
        }
    }
}

// ---------------- row-sum finalize: invl[r] = 1 / sum_32 Lpart ----------------
__global__ void __launch_bounds__(256) rowsum_final(
    const float* __restrict__ LP, float* __restrict__ invl)
{
    int r = blockIdx.x * 256 + threadIdx.x;
    float s = 0.0f;
    #pragma unroll
    for (int i = 0; i < 32; i++) s += LP[(size_t)i * TOK + r];
    invl[r] = 1.0f / s;
}

// ---------------- elementwise tf32 rounding copy ----------------
__global__ void __launch_bounds__(256) round_tf32(
    const float* __restrict__ in, float* __restrict__ out)
{
    size_t i = ((size_t)blockIdx.x * 256 + threadIdx.x) * 4;
    float4 v = *reinterpret_cast<const float4*>(in + i);
    v.x = f2tf32f(v.x); v.y = f2tf32f(v.y);
    v.z = f2tf32f(v.z); v.w = f2tf32f(v.w);
    *reinterpret_cast<float4*>(out + i) = v;
}

// ---------------- transpose (+tf32 round) ----------------
__global__ void __launch_bounds__(256) transpose_k(
    const float* __restrict__ in, float* __restrict__ out,
    int ldIn, int ldOut, size_t sIn, size_t sOut)
{
    __shared__ float t[32][33];
    in  += (size_t)blockIdx.z * sIn;
    out += (size_t)blockIdx.z * sOut;
    const int x = blockIdx.x * 32 + threadIdx.x;
    const int y0 = blockIdx.y * 32;
    #pragma unroll
    for (int j = threadIdx.y; j < 32; j += 8)
        t[j][threadIdx.x] = in[(size_t)(y0 + j) * ldIn + x];
    __syncthreads();
    const int ox = blockIdx.y * 32 + threadIdx.x;
    const int oy0 = blockIdx.x * 32;
    #pragma unroll
    for (int j = threadIdx.y; j < 32; j += 8)
        out[(size_t)(oy0 + j) * ldOut + ox] = f2tf32f(t[threadIdx.x][j]);
}

// ---------------- bias concat ----------------
__global__ void __launch_bounds__(256) concat_bias(
    const float* __restrict__ a, const float* __restrict__ b,
    const float* __restrict__ c, float* __restrict__ o)
{
    int i = blockIdx.x * 256 + threadIdx.x;   // 0..1535
    float v = (i < 512) ? a[i] : ((i < 1024) ? b[i - 512] : c[i - 1024]);
    o[i] = v;
}

// ---------------- host ----------------
extern "C" void kernel_launch(void* const* d_in, const int* in_sizes, int n_in,
                              void* d_out, int out_size)
{
    const float* x  = (const float*)d_in[0];
    const float* Wq = (const float*)d_in[1];
    const float* bq = (const float*)d_in[2];
    const float* Wk = (const float*)d_in[3];
    const float* bk = (const float*)d_in[4];
    const float* Wv = (const float*)d_in[5];
    const float* bv = (const float*)d_in[6];
    const float* Wo = (const float*)d_in[7];
    const float* bo = (const float*)d_in[8];
    float* out = (float*)d_out;

    float *X, *QKV, *Vt, *S, *O, *WT, *Bqkv, *LP, *L;
    cudaGetSymbolAddress((void**)&X,    g_X);
    cudaGetSymbolAddress((void**)&QKV,  g_QKV);
    cudaGetSymbolAddress((void**)&Vt,   g_Vt);
    cudaGetSymbolAddress((void**)&S,    g_S);
    cudaGetSymbolAddress((void**)&O,    g_O);
    cudaGetSymbolAddress((void**)&WT,   g_WT);
    cudaGetSymbolAddress((void**)&Bqkv, g_Bqkv);
    cudaGetSymbolAddress((void**)&LP,   g_Lpart);
    cudaGetSymbolAddress((void**)&L,    g_L);

    cudaFuncSetAttribute(gemm_nt<0>, cudaFuncAttributeMaxDynamicSharedMemorySize, SMEM_BYTES);
    cudaFuncSetAttribute(gemm_nt<1>, cudaFuncAttributeMaxDynamicSharedMemorySize, SMEM_BYTES);
    cudaFuncSetAttribute(gemm_nt<2>, cudaFuncAttributeMaxDynamicSharedMemorySize, SMEM_BYTES);
    cudaFuncSetAttribute(gemm_nt<3>, cudaFuncAttributeMaxDynamicSharedMemorySize, SMEM_BYTES);

    const float scale = 0.044194173824159216f;  // 1/sqrt(512)
    const size_t W2 = (size_t)EMB * EMB;

    // Round x to tf32 once
    round_tf32<<<(TOK * EMB) / (256 * 4), 256>>>(x, X);

    // Weight transposes (fused tf32 round). WT rows 0..1535 = WqT|WkT|WvT, slot 3 = WoT.
    dim3 tb(32, 8);
    dim3 tgW(EMB / 32, EMB / 32, 1);
    transpose_k<<<tgW, tb>>>(Wq, WT + 0 * W2, EMB, EMB, 0, 0);
    transpose_k<<<tgW, tb>>>(Wk, WT + 1 * W2, EMB, EMB, 0, 0);
    transpose_k<<<tgW, tb>>>(Wv, WT + 2 * W2, EMB, EMB, 0, 0);
    transpose_k<<<tgW, tb>>>(Wo, WT + 3 * W2, EMB, EMB, 0, 0);
    concat_bias<<<6, 256>>>(bq, bk, bv, Bqkv);

    // Fused QKV projection: QKV[16384,1536] = X @ [Wq|Wk|Wv] + b, rounded
    dim3 gqkv(3 * EMB / 128, TOK / 128, 1);
    gemm_nt<0><<<gqkv, 128, SMEM_BYTES>>>(
        X, WT, Bqkv, QKV, EMB, EMB, 3 * EMB, EMB, 0, 0, 0, 0, 1.0f);

    // V^T per batch: [EMB, SEQ] (V = QKV cols 1024..1535)
    dim3 tgV(EMB / 32, SEQ / 32, BATCH);
    transpose_k<<<tgV, tb>>>(QKV + 2 * EMB, Vt, 3 * EMB, SEQ,
                             (size_t)SEQ * 3 * EMB, (size_t)SEQ * EMB);

    // Scores + fused exp + row partial sums: S = exp(scale * Q @ K^T)
    dim3 gscore(SEQ / 128, SEQ / 128, BATCH);
    gemm_nt<1><<<gscore, 128, SMEM_BYTES>>>(
        QKV, QKV + EMB, nullptr, S, 3 * EMB, 3 * EMB, SEQ, EMB,
        (size_t)SEQ * 3 * EMB, (size_t)SEQ * 3 * EMB, (size_t)SEQ * SEQ, 0, scale);

    // invl[r] = 1 / sum(exp row)
    rowsum_final<<<TOK / 256, 256>>>(LP, L);

    // O[b] = (S[b] @ V[b]) * invl[row], rounded
    dim3 gav(EMB / 128, SEQ / 128, BATCH);
    gemm_nt<2><<<gav, 128, SMEM_BYTES>>>(
        S, Vt, L, O, SEQ, SEQ, EMB, SEQ,
        (size_t)SEQ * SEQ, (size_t)SEQ * EMB, (size_t)SEQ * EMB, SEQ, 1.0f);

    // Final projection: out = O @ Wo + bo (full fp32)
    dim3 gout(EMB / 128, TOK / 128, 1);
    gemm_nt<3><<<gout, 128, SMEM_BYTES>>>(
        O, WT + 3 * W2, bo, out, EMB, EMB, EMB, EMB, 0, 0, 0, 0, 1.0f);
}

// round 8
// speedup vs baseline: 1.0580x; 1.0580x over previous
#include <cuda_runtime.h>
#include <cstdint>

#define EMB 512
#define BATCH 8
#define SEQ 2048
#define TOK (BATCH * SEQ)   // 16384

// Scratch (allocation-free rule: __device__ globals)
__device__ float g_X[(size_t)TOK * EMB];
__device__ float g_QKV[(size_t)TOK * 3 * EMB];
__device__ float g_Vt[(size_t)TOK * EMB];
__device__ float g_O[(size_t)TOK * EMB];
__device__ float g_S[(size_t)BATCH * SEQ * SEQ];
__device__ float g_WT[4 * EMB * EMB];
__device__ float g_Bqkv[3 * EMB];
__device__ float g_Lpart[32 * TOK];
__device__ float g_L[TOK];

// ---------------- PTX helpers (compute_103-safe) ----------------
__device__ __forceinline__ uint32_t smem_u32(const void* p) {
    uint32_t a;
    asm("{ .reg .u64 t; cvta.to.shared.u64 t, %1; cvt.u32.u64 %0, t; }" : "=r"(a) : "l"(p));
    return a;
}
__device__ __forceinline__ void cp16(uint32_t s, const void* g) {
    asm volatile("cp.async.cg.shared.global [%0], [%1], 16;" :: "r"(s), "l"(g));
}
#define CP_COMMIT() asm volatile("cp.async.commit_group;" ::: "memory")
#define CP_WAIT0()  asm volatile("cp.async.wait_group 0;" ::: "memory")

__device__ __forceinline__ float f2tf32f(float x) {
    unsigned u; asm("cvt.rna.tf32.f32 %0, %1;" : "=r"(u) : "f"(x));
    return __uint_as_float(u);
}

// FMA-pipe exp (no MUFU): x ~ [-16,16], rel err ~2e-6.
__device__ __forceinline__ float fexp(float x) {
    float t = x * 1.4426950408889634f;
    float r = rintf(t);
    float f = t - r;
    float p =          1.3333558146428443e-3f;
    p = fmaf(p, f,     9.6181291076284772e-3f);
    p = fmaf(p, f,     5.5504108664821580e-2f);
    p = fmaf(p, f,     2.4022650695910071e-1f);
    p = fmaf(p, f,     6.9314718055994531e-1f);
    p = fmaf(p, f,     1.0f);
    int i = (int)r;
    return p * __int_as_float((i + 127) << 23);
}

__device__ __forceinline__ void mma_tf32(float* d, const unsigned* a, unsigned b0, unsigned b1) {
    asm volatile(
        "mma.sync.aligned.m16n8k8.row.col.f32.tf32.tf32.f32 "
        "{%0,%1,%2,%3}, {%4,%5,%6,%7}, {%8,%9}, {%0,%1,%2,%3};"
        : "+f"(d[0]), "+f"(d[1]), "+f"(d[2]), "+f"(d[3])
        : "r"(a[0]), "r"(a[1]), "r"(a[2]), "r"(a[3]), "r"(b0), "r"(b1));
}

// ---------------- NT tf32 GEMM ----------------
// C = scale * A @ B^T (+epilogue). Pre-rounded tf32 operands. Block tile
// 128x128, BK=32, 8 warps (4x2), warp tile 32x64, 2-stage cp.async pipeline,
// 2 CTAs/SM (16 warps/SM = 4/SMSP for stall hiding), stride-36 smem,
// ONE __syncthreads per k-tile.
// EPI: 0 = +bias, round (QKV proj)   1 = exp, row-partial-sums, round (score)
//      2 = *invl[row], round (AV)    3 = +bias (final)
#define BK 32
#define STRIDE 36
#define TILE_FLOATS (128 * STRIDE)           // 4608
#define STAGE_FLOATS (2 * TILE_FLOATS)       // 9216
#define SMEM_BYTES (2 * STAGE_FLOATS * 4)    // 73728

template <int EPI>
__global__ void __launch_bounds__(256, 2) gemm_nt(
    const float* __restrict__ A, const float* __restrict__ B,
    const float* __restrict__ aux, float* __restrict__ C,
    int lda, int ldb, int ldc, int K,
    size_t sA, size_t sB, size_t sC, int sAux, float scale)
{
    extern __shared__ float smem[];
    const uint32_t sbase = smem_u32(smem);

    const int tid  = threadIdx.x;
    const int lane = tid & 31;
    const int warp = tid >> 5;
    const int wr = (warp & 3) * 32;   // warp row offset (4 row-warps)
    const int wc = (warp >> 2) * 64;  // warp col offset (2 col-warps)

    const int b = blockIdx.z;
    A += (size_t)b * sA;
    B += (size_t)b * sB;
    C += (size_t)b * sC;
    if (aux) aux += (size_t)b * sAux;
    const int row0 = blockIdx.y * 128;
    const int col0 = blockIdx.x * 128;

    float acc[2][8][4];
    #pragma unroll
    for (int mi = 0; mi < 2; mi++)
        #pragma unroll
        for (int ni = 0; ni < 8; ni++)
            #pragma unroll
            for (int j = 0; j < 4; j++) acc[mi][ni][j] = 0.0f;

    const float* gA = A + (size_t)row0 * lda;
    const float* gB = B + (size_t)col0 * ldb;
    const int frow0 = tid >> 3;      // 0..31
    const int fkq   = tid & 7;       // 16B chunk within 128B row

    auto fill = [&](int t, int buf) {
        uint32_t smA = sbase + (uint32_t)buf * STAGE_FLOATS * 4;
        uint32_t smB = smA + TILE_FLOATS * 4;
        const float* pa = gA + t * BK + fkq * 4;
        const float* pb = gB + t * BK + fkq * 4;
        int row = frow0;
        #pragma unroll
        for (int it = 0; it < 4; it++, row += 32) {
            uint32_t off = (uint32_t)(row * STRIDE + fkq * 4) * 4;
            cp16(smA + off, pa + (size_t)row * lda);
            cp16(smB + off, pb + (size_t)row * ldb);
        }
    };

    const int ktiles = K / BK;
    fill(0, 0); CP_COMMIT();

    const int g = lane >> 2;
    const int q = lane & 3;

    for (int t = 0; t < ktiles; t++) {
        CP_WAIT0();             // stage t resident
        __syncthreads();        // all warps done computing t-1 -> its buffer is free
        if (t + 1 < ktiles) { fill(t + 1, (t + 1) & 1); CP_COMMIT(); }

        const float* sA_ = smem + (t & 1) * STAGE_FLOATS;
        const float* sB_ = sA_ + TILE_FLOATS;

        #pragma unroll
        for (int ks = 0; ks < 4; ks++) {
            const int kc = ks * 8 + q;
            unsigned a[2][4];
            #pragma unroll
            for (int mi = 0; mi < 2; mi++) {
                int r = wr + mi * 16 + g;
                a[mi][0] = __float_as_uint(sA_[r * STRIDE + kc]);
                a[mi][1] = __float_as_uint(sA_[(r + 8) * STRIDE + kc]);
                a[mi][2] = __float_as_uint(sA_[r * STRIDE + kc + 4]);
                a[mi][3] = __float_as_uint(sA_[(r + 8) * STRIDE + kc + 4]);
            }
            #pragma unroll
            for (int ni = 0; ni < 8; ni++) {
                int n = wc + ni * 8 + g;
                unsigned b0 = __float_as_uint(sB_[n * STRIDE + kc]);
                unsigned b1 = __float_as_uint(sB_[n * STRIDE + kc + 4]);
                #pragma unroll
                for (int mi = 0; mi < 2; mi++)
                    mma_tf32(acc[mi][ni], a[mi], b0, b1);
            }
        }
    }

    // Epilogue
    float rs0[2], rs1[2];
    #pragma unroll
    for (int mi = 0; mi < 2; mi++) { rs0[mi] = 0.0f; rs1[mi] = 0.0f; }

    #pragma unroll
    for (int mi = 0; mi < 2; mi++) {
        int rloc = wr + mi * 16 + g;
        int r = row0 + rloc;
        float il0 = 1.0f, il1 = 1.0f;
        if (EPI == 2) { il0 = aux[r]; il1 = aux[r + 8]; }
        float* c0 = C + (size_t)r * ldc + col0;
        float* c1 = c0 + (size_t)8 * ldc;
        #pragma unroll
        for (int ni = 0; ni < 8; ni++) {
            int c = wc + ni * 8 + 2 * q;
            float2 v0, v1;
            v0.x = acc[mi][ni][0] * scale;
            v0.y = acc[mi][ni][1] * scale;
            v1.x = acc[mi][ni][2] * scale;
            v1.y = acc[mi][ni][3] * scale;
            if (EPI == 0 || EPI == 3) {
                float bx = aux[col0 + c], by = aux[col0 + c + 1];
                v0.x += bx; v0.y += by;
                v1.x += bx; v1.y += by;
            }
            if (EPI == 1) {
                v0.x = fexp(v0.x); v0.y = fexp(v0.y);
                v1.x = fexp(v1.x); v1.y = fexp(v1.y);
                rs0[mi] += v0.x + v0.y;
                rs1[mi] += v1.x + v1.y;
            }
            if (EPI == 2) {
                v0.x *= il0; v0.y *= il0;
                v1.x *= il1; v1.y *= il1;
            }
            if (EPI != 3) {
                v0.x = f2tf32f(v0.x); v0.y = f2tf32f(v0.y);
                v1.x = f2tf32f(v1.x); v1.y = f2tf32f(v1.y);
            }
            *reinterpret_cast<float2*>(c0 + c) = v0;
            *reinterpret_cast<float2*>(c1 + c) = v1;
        }
    }

    if (EPI == 1) {
        // reduce partial row sums across q (4 lanes per row), write Lpart.
        // Two col-warps (warp>>2) hold different column halves of each row.
        #pragma unroll
        for (int mi = 0; mi < 2; mi++) {
            rs0[mi] += __shfl_xor_sync(0xFFFFFFFF, rs0[mi], 1);
            rs0[mi] += __shfl_xor_sync(0xFFFFFFFF, rs0[mi], 2);
            rs1[mi] += __shfl_xor_sync(0xFFFFFFFF, rs1[mi], 1);
            rs1[mi] += __shfl_xor_sync(0xFFFFFFFF, rs1[mi], 2);
        }
        if (q == 0) {
            int slot = blockIdx.x * 2 + (warp >> 2);
            size_t base = (size_t)slot * TOK + (size_t)b * SEQ + row0 + wr;
            #pragma unroll
            for (int mi = 0; mi < 2; mi++) {
                g_Lpart[base + mi * 16 + g]     = rs0[mi];
                g_Lpart[base + mi * 16 + g + 8] = rs1[mi];
            }
        }
    }
}

// ---------------- row-sum finalize: invl[r] = 1 / sum_32 Lpart ----------------
__global__ void __launch_bounds__(256) rowsum_final(
    const float* __restrict__ LP, float* __restrict__ invl)
{
    int r = blockIdx.x * 256 + threadIdx.x;
    float s = 0.0f;
    #pragma unroll
    for (int i = 0; i < 32; i++) s += LP[(size_t)i * TOK + r];
    invl[r] = 1.0f / s;
}

// ---------------- elementwise tf32 rounding copy ----------------
__global__ void __launch_bounds__(256) round_tf32(
    const float* __restrict__ in, float* __restrict__ out)
{
    size_t i = ((size_t)blockIdx.x * 256 + threadIdx.x) * 4;
    float4 v = *reinterpret_cast<const float4*>(in + i);
    v.x = f2tf32f(v.x); v.y = f2tf32f(v.y);
    v.z = f2tf32f(v.z); v.w = f2tf32f(v.w);
    *reinterpret_cast<float4*>(out + i) = v;
}

// ---------------- transpose (+tf32 round) ----------------
__global__ void __launch_bounds__(256) transpose_k(
    const float* __restrict__ in, float* __restrict__ out,
    int ldIn, int ldOut, size_t sIn, size_t sOut)
{
    __shared__ float t[32][33];
    in  += (size_t)blockIdx.z * sIn;
    out += (size_t)blockIdx.z * sOut;
    const int x = blockIdx.x * 32 + threadIdx.x;
    const int y0 = blockIdx.y * 32;
    #pragma unroll
    for (int j = threadIdx.y; j < 32; j += 8)
        t[j][threadIdx.x] = in[(size_t)(y0 + j) * ldIn + x];
    __syncthreads();
    const int ox = blockIdx.y * 32 + threadIdx.x;
    const int oy0 = blockIdx.x * 32;
    #pragma unroll
    for (int j = threadIdx.y; j < 32; j += 8)
        out[(size_t)(oy0 + j) * ldOut + ox] = f2tf32f(t[threadIdx.x][j]);
}

// ---------------- bias concat ----------------
__global__ void __launch_bounds__(256) concat_bias(
    const float* __restrict__ a, const float* __restrict__ b,
    const float* __restrict__ c, float* __restrict__ o)
{
    int i = blockIdx.x * 256 + threadIdx.x;   // 0..1535
    float v = (i < 512) ? a[i] : ((i < 1024) ? b[i - 512] : c[i - 1024]);
    o[i] = v;
}

// ---------------- host ----------------
extern "C" void kernel_launch(void* const* d_in, const int* in_sizes, int n_in,
                              void* d_out, int out_size)
{
    const float* x  = (const float*)d_in[0];
    const float* Wq = (const float*)d_in[1];
    const float* bq = (const float*)d_in[2];
    const float* Wk = (const float*)d_in[3];
    const float* bk = (const float*)d_in[4];
    const float* Wv = (const float*)d_in[5];
    const float* bv = (const float*)d_in[6];
    const float* Wo = (const float*)d_in[7];
    const float* bo = (const float*)d_in[8];
    float* out = (float*)d_out;

    float *X, *QKV, *Vt, *S, *O, *WT, *Bqkv, *LP, *L;
    cudaGetSymbolAddress((void**)&X,    g_X);
    cudaGetSymbolAddress((void**)&QKV,  g_QKV);
    cudaGetSymbolAddress((void**)&Vt,   g_Vt);
    cudaGetSymbolAddress((void**)&S,    g_S);
    cudaGetSymbolAddress((void**)&O,    g_O);
    cudaGetSymbolAddress((void**)&WT,   g_WT);
    cudaGetSymbolAddress((void**)&Bqkv, g_Bqkv);
    cudaGetSymbolAddress((void**)&LP,   g_Lpart);
    cudaGetSymbolAddress((void**)&L,    g_L);

    cudaFuncSetAttribute(gemm_nt<0>, cudaFuncAttributeMaxDynamicSharedMemorySize, SMEM_BYTES);
    cudaFuncSetAttribute(gemm_nt<1>, cudaFuncAttributeMaxDynamicSharedMemorySize, SMEM_BYTES);
    cudaFuncSetAttribute(gemm_nt<2>, cudaFuncAttributeMaxDynamicSharedMemorySize, SMEM_BYTES);
    cudaFuncSetAttribute(gemm_nt<3>, cudaFuncAttributeMaxDynamicSharedMemorySize, SMEM_BYTES);

    const float scale = 0.044194173824159216f;  // 1/sqrt(512)
    const size_t W2 = (size_t)EMB * EMB;

    // Round x to tf32 once
    round_tf32<<<(TOK * EMB) / (256 * 4), 256>>>(x, X);

    // Weight transposes (fused tf32 round). WT rows 0..1535 = WqT|WkT|WvT, slot 3 = WoT.
    dim3 tb(32, 8);
    dim3 tgW(EMB / 32, EMB / 32, 1);
    transpose_k<<<tgW, tb>>>(Wq, WT + 0 * W2, EMB, EMB, 0, 0);
    transpose_k<<<tgW, tb>>>(Wk, WT + 1 * W2, EMB, EMB, 0, 0);
    transpose_k<<<tgW, tb>>>(Wv, WT + 2 * W2, EMB, EMB, 0, 0);
    transpose_k<<<tgW, tb>>>(Wo, WT + 3 * W2, EMB, EMB, 0, 0);
    concat_bias<<<6, 256>>>(bq, bk, bv, Bqkv);

    // Fused QKV projection: QKV[16384,1536] = X @ [Wq|Wk|Wv] + b, rounded
    dim3 gqkv(3 * EMB / 128, TOK / 128, 1);
    gemm_nt<0><<<gqkv, 256, SMEM_BYTES>>>(
        X, WT, Bqkv, QKV, EMB, EMB, 3 * EMB, EMB, 0, 0, 0, 0, 1.0f);

    // V^T per batch: [EMB, SEQ] (V = QKV cols 1024..1535)
    dim3 tgV(EMB / 32, SEQ / 32, BATCH);
    transpose_k<<<tgV, tb>>>(QKV + 2 * EMB, Vt, 3 * EMB, SEQ,
                             (size_t)SEQ * 3 * EMB, (size_t)SEQ * EMB);

    // Scores + fused exp + row partial sums: S = exp(scale * Q @ K^T)
    dim3 gscore(SEQ / 128, SEQ / 128, BATCH);
    gemm_nt<1><<<gscore, 256, SMEM_BYTES>>>(
        QKV, QKV + EMB, nullptr, S, 3 * EMB, 3 * EMB, SEQ, EMB,
        (size_t)SEQ * 3 * EMB, (size_t)SEQ * 3 * EMB, (size_t)SEQ * SEQ, 0, scale);

    // invl[r] = 1 / sum(exp row)
    rowsum_final<<<TOK / 256, 256>>>(LP, L);

    // O[b] = (S[b] @ V[b]) * invl[row], rounded
    dim3 gav(EMB / 128, SEQ / 128, BATCH);
    gemm_nt<2><<<gav, 256, SMEM_BYTES>>>(
        S, Vt, L, O, SEQ, SEQ, EMB, SEQ,
        (size_t)SEQ * SEQ, (size_t)SEQ * EMB, (size_t)SEQ * EMB, SEQ, 1.0f);

    // Final projection: out = O @ Wo + bo (full fp32)
    dim3 gout(EMB / 128, TOK / 128, 1);
    gemm_nt<3><<<gout, 256, SMEM_BYTES>>>(
        O, WT + 3 * W2, bo, out, EMB, EMB, EMB, EMB, 0, 0, 0, 0, 1.0f);
}

// round 9
// speedup vs baseline: 1.8619x; 1.7599x over previous
#include <cuda_runtime.h>
#include <cuda_fp16.h>
#include <cstdint>

#define EMB 512
#define BATCH 8
#define SEQ 2048
#define TOK (BATCH * SEQ)   // 16384

// Scratch (allocation-free rule: __device__ globals)
__device__ __half g_Xh[(size_t)TOK * EMB];
__device__ __half g_QKV[(size_t)TOK * 3 * EMB];
__device__ __half g_Vt[(size_t)TOK * EMB];
__device__ __half g_O[(size_t)TOK * EMB];
__device__ __half g_S[(size_t)BATCH * SEQ * SEQ];
__device__ __half g_WT[4 * EMB * EMB];
__device__ float  g_Bqkv[3 * EMB];
__device__ float  g_Lpart[32 * TOK];
__device__ float  g_L[TOK];

// ---------------- PTX helpers (compute_103-safe) ----------------
__device__ __forceinline__ uint32_t smem_u32(const void* p) {
    uint32_t a;
    asm("{ .reg .u64 t; cvta.to.shared.u64 t, %1; cvt.u32.u64 %0, t; }" : "=r"(a) : "l"(p));
    return a;
}
__device__ __forceinline__ void cp16(uint32_t s, const void* g) {
    asm volatile("cp.async.cg.shared.global [%0], [%1], 16;" :: "r"(s), "l"(g));
}
#define CP_COMMIT() asm volatile("cp.async.commit_group;" ::: "memory")
#define CP_WAIT0()  asm volatile("cp.async.wait_group 0;" ::: "memory")

// FMA-pipe exp (no MUFU): x ~ [-16,16], rel err ~2e-6.
__device__ __forceinline__ float fexp(float x) {
    float t = x * 1.4426950408889634f;
    float r = rintf(t);
    float f = t - r;
    float p =          1.3333558146428443e-3f;
    p = fmaf(p, f,     9.6181291076284772e-3f);
    p = fmaf(p, f,     5.5504108664821580e-2f);
    p = fmaf(p, f,     2.4022650695910071e-1f);
    p = fmaf(p, f,     6.9314718055994531e-1f);
    p = fmaf(p, f,     1.0f);
    int i = (int)r;
    return p * __int_as_float((i + 127) << 23);
}

// fp16 MMA m16n8k16, fp32 accumulate.
__device__ __forceinline__ void mma_f16(float* d, const uint32_t* a, uint32_t b0, uint32_t b1) {
    asm volatile(
        "mma.sync.aligned.m16n8k16.row.col.f32.f16.f16.f32 "
        "{%0,%1,%2,%3}, {%4,%5,%6,%7}, {%8,%9}, {%0,%1,%2,%3};"
        : "+f"(d[0]), "+f"(d[1]), "+f"(d[2]), "+f"(d[3])
        : "r"(a[0]), "r"(a[1]), "r"(a[2]), "r"(a[3]), "r"(b0), "r"(b1));
}

// ---------------- NT fp16 GEMM (fp32 accum) ----------------
// C = scale * A @ B^T (+epilogue). A [M,lda], B [N,ldb] halves, K-major.
// Block tile 128x128, BK=64 halves (128B rows), 8 warps (4x2), warp tile
// 32x64, 2-stage cp.async, 2 CTAs/SM, stride-72 smem (conflict-free).
// EPI: 0 = +bias, ->half (QKV)   1 = exp, row-partial-sums, ->half (score)
//      2 = *invl[row], ->half (AV)   3 = +bias, ->float (final)
#define BK 64
#define STR 72
#define TILE_HALFS (128 * STR)               // 9216
#define STAGE_HALFS (2 * TILE_HALFS)         // 18432
#define SMEM_BYTES (2 * STAGE_HALFS * 2)     // 73728

template <int EPI>
__global__ void __launch_bounds__(256, 2) gemm_nt(
    const __half* __restrict__ A, const __half* __restrict__ B,
    const float* __restrict__ aux, void* __restrict__ Cv,
    int lda, int ldb, int ldc, int K,
    size_t sA, size_t sB, size_t sC, int sAux, float scale)
{
    extern __shared__ __half smem[];
    const uint32_t sbase = smem_u32(smem);

    const int tid  = threadIdx.x;
    const int lane = tid & 31;
    const int warp = tid >> 5;
    const int wr = (warp & 3) * 32;
    const int wc = (warp >> 2) * 64;

    const int b = blockIdx.z;
    A += (size_t)b * sA;
    B += (size_t)b * sB;
    if (aux) aux += (size_t)b * sAux;
    const int row0 = blockIdx.y * 128;
    const int col0 = blockIdx.x * 128;

    float acc[2][8][4];
    #pragma unroll
    for (int mi = 0; mi < 2; mi++)
        #pragma unroll
        for (int ni = 0; ni < 8; ni++)
            #pragma unroll
            for (int j = 0; j < 4; j++) acc[mi][ni][j] = 0.0f;

    const __half* gA = A + (size_t)row0 * lda;
    const __half* gB = B + (size_t)col0 * ldb;

    auto fill = [&](int t, int buf) {
        uint32_t smA = sbase + (uint32_t)buf * STAGE_HALFS * 2;
        uint32_t smB = smA + TILE_HALFS * 2;
        const __half* pa = gA + t * BK;
        const __half* pb = gB + t * BK;
        #pragma unroll
        for (int it = 0; it < 4; it++) {
            int idx = tid + it * 256;        // 0..1023
            int row = idx >> 3, cq = idx & 7;
            uint32_t off = 2u * (uint32_t)(row * STR + cq * 8);
            cp16(smA + off, pa + (size_t)row * lda + cq * 8);
            cp16(smB + off, pb + (size_t)row * ldb + cq * 8);
        }
    };

    const int ktiles = K / BK;
    fill(0, 0); CP_COMMIT();

    const int g = lane >> 2;
    const int q = lane & 3;

    for (int t = 0; t < ktiles; t++) {
        CP_WAIT0();             // stage t resident
        __syncthreads();        // all warps done with t-1 -> buffer free
        if (t + 1 < ktiles) { fill(t + 1, (t + 1) & 1); CP_COMMIT(); }

        const __half* sA_ = smem + (t & 1) * STAGE_HALFS;
        const __half* sB_ = sA_ + TILE_HALFS;

        #pragma unroll
        for (int ks = 0; ks < 4; ks++) {      // 4 x k16
            const int kc = ks * 16 + 2 * q;
            uint32_t a[2][4];
            #pragma unroll
            for (int mi = 0; mi < 2; mi++) {
                int r = wr + mi * 16 + g;
                a[mi][0] = *reinterpret_cast<const uint32_t*>(&sA_[r * STR + kc]);
                a[mi][1] = *reinterpret_cast<const uint32_t*>(&sA_[(r + 8) * STR + kc]);
                a[mi][2] = *reinterpret_cast<const uint32_t*>(&sA_[r * STR + kc + 8]);
                a[mi][3] = *reinterpret_cast<const uint32_t*>(&sA_[(r + 8) * STR + kc + 8]);
            }
            #pragma unroll
            for (int ni = 0; ni < 8; ni++) {
                int n = wc + ni * 8 + g;
                uint32_t b0 = *reinterpret_cast<const uint32_t*>(&sB_[n * STR + kc]);
                uint32_t b1 = *reinterpret_cast<const uint32_t*>(&sB_[n * STR + kc + 8]);
                #pragma unroll
                for (int mi = 0; mi < 2; mi++)
                    mma_f16(acc[mi][ni], a[mi], b0, b1);
            }
        }
    }

    // Epilogue
    float rs0[2], rs1[2];
    #pragma unroll
    for (int mi = 0; mi < 2; mi++) { rs0[mi] = 0.0f; rs1[mi] = 0.0f; }

    #pragma unroll
    for (int mi = 0; mi < 2; mi++) {
        int rloc = wr + mi * 16 + g;
        int r = row0 + rloc;
        float il0 = 1.0f, il1 = 1.0f;
        if (EPI == 2) { il0 = aux[r]; il1 = aux[r + 8]; }
        #pragma unroll
        for (int ni = 0; ni < 8; ni++) {
            int c = wc + ni * 8 + 2 * q;
            float2 v0, v1;
            v0.x = acc[mi][ni][0] * scale;
            v0.y = acc[mi][ni][1] * scale;
            v1.x = acc[mi][ni][2] * scale;
            v1.y = acc[mi][ni][3] * scale;
            if (EPI == 0 || EPI == 3) {
                float bx = aux[col0 + c], by = aux[col0 + c + 1];
                v0.x += bx; v0.y += by;
                v1.x += bx; v1.y += by;
            }
            if (EPI == 1) {
                v0.x = fexp(v0.x); v0.y = fexp(v0.y);
                v1.x = fexp(v1.x); v1.y = fexp(v1.y);
                rs0[mi] += v0.x + v0.y;
                rs1[mi] += v1.x + v1.y;
            }
            if (EPI == 2) {
                v0.x *= il0; v0.y *= il0;
                v1.x *= il1; v1.y *= il1;
            }
            if (EPI == 3) {
                float* c0 = (float*)Cv + (size_t)b * sC + (size_t)r * ldc + col0;
                float* c1 = c0 + (size_t)8 * ldc;
                *reinterpret_cast<float2*>(c0 + c) = v0;
                *reinterpret_cast<float2*>(c1 + c) = v1;
            } else {
                __half* c0 = (__half*)Cv + (size_t)b * sC + (size_t)r * ldc + col0;
                __half* c1 = c0 + (size_t)8 * ldc;
                *reinterpret_cast<__half2*>(c0 + c) = __floats2half2_rn(v0.x, v0.y);
                *reinterpret_cast<__half2*>(c1 + c) = __floats2half2_rn(v1.x, v1.y);
            }
        }
    }

    if (EPI == 1) {
        // reduce partial row sums across q (4 lanes per row), write Lpart
        #pragma unroll
        for (int mi = 0; mi < 2; mi++) {
            rs0[mi] += __shfl_xor_sync(0xFFFFFFFF, rs0[mi], 1);
            rs0[mi] += __shfl_xor_sync(0xFFFFFFFF, rs0[mi], 2);
            rs1[mi] += __shfl_xor_sync(0xFFFFFFFF, rs1[mi], 1);
            rs1[mi] += __shfl_xor_sync(0xFFFFFFFF, rs1[mi], 2);
        }
        if (q == 0) {
            int slot = blockIdx.x * 2 + (warp >> 2);
            size_t base = (size_t)slot * TOK + (size_t)b * SEQ + row0 + wr;
            #pragma unroll
            for (int mi = 0; mi < 2; mi++) {
                g_Lpart[base + mi * 16 + g]     = rs0[mi];
                g_Lpart[base + mi * 16 + g + 8] = rs1[mi];
            }
        }
    }
}

// ---------------- row-sum finalize: invl[r] = 1 / sum_32 Lpart ----------------
__global__ void __launch_bounds__(256) rowsum_final(
    const float* __restrict__ LP, float* __restrict__ invl)
{
    int r = blockIdx.x * 256 + threadIdx.x;
    float s = 0.0f;
    #pragma unroll
    for (int i = 0; i < 32; i++) s += LP[(size_t)i * TOK + r];
    invl[r] = 1.0f / s;
}

// ---------------- fp32 -> fp16 copy ----------------
__global__ void __launch_bounds__(256) round_h(
    const float* __restrict__ in, __half* __restrict__ out)
{
    size_t i = ((size_t)blockIdx.x * 256 + threadIdx.x) * 8;
    float4 v0 = *reinterpret_cast<const float4*>(in + i);
    float4 v1 = *reinterpret_cast<const float4*>(in + i + 4);
    __half2 h[4];
    h[0] = __floats2half2_rn(v0.x, v0.y);
    h[1] = __floats2half2_rn(v0.z, v0.w);
    h[2] = __floats2half2_rn(v1.x, v1.y);
    h[3] = __floats2half2_rn(v1.z, v1.w);
    *reinterpret_cast<uint4*>(out + i) = *reinterpret_cast<uint4*>(h);
}

// ---------------- transposes ----------------
__global__ void __launch_bounds__(256) transpose_f2h(
    const float* __restrict__ in, __half* __restrict__ out,
    int ldIn, int ldOut)
{
    __shared__ float t[32][33];
    const int x = blockIdx.x * 32 + threadIdx.x;
    const int y0 = blockIdx.y * 32;
    #pragma unroll
    for (int j = threadIdx.y; j < 32; j += 8)
        t[j][threadIdx.x] = in[(size_t)(y0 + j) * ldIn + x];
    __syncthreads();
    const int ox = blockIdx.y * 32 + threadIdx.x;
    const int oy0 = blockIdx.x * 32;
    #pragma unroll
    for (int j = threadIdx.y; j < 32; j += 8)
        out[(size_t)(oy0 + j) * ldOut + ox] = __float2half_rn(t[threadIdx.x][j]);
}

__global__ void __launch_bounds__(256) transpose_h2h(
    const __half* __restrict__ in, __half* __restrict__ out,
    int ldIn, int ldOut, size_t sIn, size_t sOut)
{
    __shared__ __half t[32][34];
    in  += (size_t)blockIdx.z * sIn;
    out += (size_t)blockIdx.z * sOut;
    const int x = blockIdx.x * 32 + threadIdx.x;
    const int y0 = blockIdx.y * 32;
    #pragma unroll
    for (int j = threadIdx.y; j < 32; j += 8)
        t[j][threadIdx.x] = in[(size_t)(y0 + j) * ldIn + x];
    __syncthreads();
    const int ox = blockIdx.y * 32 + threadIdx.x;
    const int oy0 = blockIdx.x * 32;
    #pragma unroll
    for (int j = threadIdx.y; j < 32; j += 8)
        out[(size_t)(oy0 + j) * ldOut + ox] = t[threadIdx.x][j];
}

// ---------------- bias concat ----------------
__global__ void __launch_bounds__(256) concat_bias(
    const float* __restrict__ a, const float* __restrict__ b,
    const float* __restrict__ c, float* __restrict__ o)
{
    int i = blockIdx.x * 256 + threadIdx.x;   // 0..1535
    float v = (i < 512) ? a[i] : ((i < 1024) ? b[i - 512] : c[i - 1024]);
    o[i] = v;
}

// ---------------- host ----------------
extern "C" void kernel_launch(void* const* d_in, const int* in_sizes, int n_in,
                              void* d_out, int out_size)
{
    const float* x  = (const float*)d_in[0];
    const float* Wq = (const float*)d_in[1];
    const float* bq = (const float*)d_in[2];
    const float* Wk = (const float*)d_in[3];
    const float* bk = (const float*)d_in[4];
    const float* Wv = (const float*)d_in[5];
    const float* bv = (const float*)d_in[6];
    const float* Wo = (const float*)d_in[7];
    const float* bo = (const float*)d_in[8];
    float* out = (float*)d_out;

    __half *Xh, *QKV, *Vt, *S, *O, *WT;
    float *Bqkv, *LP, *L;
    cudaGetSymbolAddress((void**)&Xh,   g_Xh);
    cudaGetSymbolAddress((void**)&QKV,  g_QKV);
    cudaGetSymbolAddress((void**)&Vt,   g_Vt);
    cudaGetSymbolAddress((void**)&S,    g_S);
    cudaGetSymbolAddress((void**)&O,    g_O);
    cudaGetSymbolAddress((void**)&WT,   g_WT);
    cudaGetSymbolAddress((void**)&Bqkv, g_Bqkv);
    cudaGetSymbolAddress((void**)&LP,   g_Lpart);
    cudaGetSymbolAddress((void**)&L,    g_L);

    cudaFuncSetAttribute(gemm_nt<0>, cudaFuncAttributeMaxDynamicSharedMemorySize, SMEM_BYTES);
    cudaFuncSetAttribute(gemm_nt<1>, cudaFuncAttributeMaxDynamicSharedMemorySize, SMEM_BYTES);
    cudaFuncSetAttribute(gemm_nt<2>, cudaFuncAttributeMaxDynamicSharedMemorySize, SMEM_BYTES);
    cudaFuncSetAttribute(gemm_nt<3>, cudaFuncAttributeMaxDynamicSharedMemorySize, SMEM_BYTES);

    const float scale = 0.044194173824159216f;  // 1/sqrt(512)
    const size_t W2 = (size_t)EMB * EMB;

    // x -> fp16
    round_h<<<(TOK * EMB) / (256 * 8), 256>>>(x, Xh);

    // Weight transposes (fp32 -> fp16). WT rows 0..1535 = WqT|WkT|WvT, slot 3 = WoT.
    dim3 tb(32, 8);
    dim3 tgW(EMB / 32, EMB / 32, 1);
    transpose_f2h<<<tgW, tb>>>(Wq, WT + 0 * W2, EMB, EMB);
    transpose_f2h<<<tgW, tb>>>(Wk, WT + 1 * W2, EMB, EMB);
    transpose_f2h<<<tgW, tb>>>(Wv, WT + 2 * W2, EMB, EMB);
    transpose_f2h<<<tgW, tb>>>(Wo, WT + 3 * W2, EMB, EMB);
    concat_bias<<<6, 256>>>(bq, bk, bv, Bqkv);

    // Fused QKV projection: QKV[16384,1536] = Xh @ [Wq|Wk|Wv] + b -> fp16
    dim3 gqkv(3 * EMB / 128, TOK / 128, 1);
    gemm_nt<0><<<gqkv, 256, SMEM_BYTES>>>(
        Xh, WT, Bqkv, QKV, EMB, EMB, 3 * EMB, EMB, 0, 0, 0, 0, 1.0f);

    // V^T per batch: [EMB, SEQ] (V = QKV cols 1024..1535)
    dim3 tgV(EMB / 32, SEQ / 32, BATCH);
    transpose_h2h<<<tgV, tb>>>(QKV + 2 * EMB, Vt, 3 * EMB, SEQ,
                               (size_t)SEQ * 3 * EMB, (size_t)SEQ * EMB);

    // Scores + fused exp + row partial sums: S = exp(scale * Q @ K^T) -> fp16
    dim3 gscore(SEQ / 128, SEQ / 128, BATCH);
    gemm_nt<1><<<gscore, 256, SMEM_BYTES>>>(
        QKV, QKV + EMB, nullptr, S, 3 * EMB, 3 * EMB, SEQ, EMB,
        (size_t)SEQ * 3 * EMB, (size_t)SEQ * 3 * EMB, (size_t)SEQ * SEQ, 0, scale);

    // invl[r] = 1 / sum(exp row)
    rowsum_final<<<TOK / 256, 256>>>(LP, L);

    // O[b] = (S[b] @ V[b]) * invl[row] -> fp16
    dim3 gav(EMB / 128, SEQ / 128, BATCH);
    gemm_nt<2><<<gav, 256, SMEM_BYTES>>>(
        S, Vt, L, O, SEQ, SEQ, EMB, SEQ,
        (size_t)SEQ * SEQ, (size_t)SEQ * EMB, (size_t)SEQ * EMB, SEQ, 1.0f);

    // Final projection: out = O @ Wo + bo (fp32 out)
    dim3 gout(EMB / 128, TOK / 128, 1);
    gemm_nt<3><<<gout, 256, SMEM_BYTES>>>(
        O, WT + 3 * W2, bo, out, EMB, EMB, EMB, EMB, 0, 0, 0, 0, 1.0f);
}

// round 10
// speedup vs baseline: 1.9818x; 1.0644x over previous
#include <cuda_runtime.h>
#include <cuda_fp16.h>
#include <cstdint>

#define EMB 512
#define BATCH 8
#define SEQ 2048
#define TOK (BATCH * SEQ)   // 16384

// Scratch (allocation-free rule: __device__ globals)
__device__ __half g_Xh[(size_t)TOK * EMB];
__device__ __half g_QKV[(size_t)TOK * 3 * EMB];
__device__ __half g_Vt[(size_t)TOK * EMB];
__device__ __half g_O[(size_t)TOK * EMB];
__device__ __half g_S[(size_t)BATCH * SEQ * SEQ];
__device__ __half g_WT[4 * EMB * EMB];
__device__ float  g_Bqkv[3 * EMB];
__device__ float  g_Lpart[32 * TOK];
__device__ float  g_L[TOK];

// ---------------- PTX helpers (compute_103-safe) ----------------
__device__ __forceinline__ uint32_t smem_u32(const void* p) {
    uint32_t a;
    asm("{ .reg .u64 t; cvta.to.shared.u64 t, %1; cvt.u32.u64 %0, t; }" : "=r"(a) : "l"(p));
    return a;
}
__device__ __forceinline__ void cp16(uint32_t s, const void* g) {
    asm volatile("cp.async.cg.shared.global [%0], [%1], 16;" :: "r"(s), "l"(g));
}
#define CP_COMMIT() asm volatile("cp.async.commit_group;" ::: "memory")
#define CP_WAIT0()  asm volatile("cp.async.wait_group 0;" ::: "memory")

#define LDSM4(r0, r1, r2, r3, addr)                                            \
    asm volatile("ldmatrix.sync.aligned.m8n8.x4.shared.b16 {%0,%1,%2,%3}, [%4];" \
        : "=r"(r0), "=r"(r1), "=r"(r2), "=r"(r3) : "r"(addr))

// FMA-pipe exp (no MUFU): x ~ [-16,16], rel err ~2e-6.
__device__ __forceinline__ float fexp(float x) {
    float t = x * 1.4426950408889634f;
    float r = rintf(t);
    float f = t - r;
    float p =          1.3333558146428443e-3f;
    p = fmaf(p, f,     9.6181291076284772e-3f);
    p = fmaf(p, f,     5.5504108664821580e-2f);
    p = fmaf(p, f,     2.4022650695910071e-1f);
    p = fmaf(p, f,     6.9314718055994531e-1f);
    p = fmaf(p, f,     1.0f);
    int i = (int)r;
    return p * __int_as_float((i + 127) << 23);
}

// fp16 MMA m16n8k16, fp32 accumulate.
__device__ __forceinline__ void mma_f16(float* d, const uint32_t* a, uint32_t b0, uint32_t b1) {
    asm volatile(
        "mma.sync.aligned.m16n8k16.row.col.f32.f16.f16.f32 "
        "{%0,%1,%2,%3}, {%4,%5,%6,%7}, {%8,%9}, {%0,%1,%2,%3};"
        : "+f"(d[0]), "+f"(d[1]), "+f"(d[2]), "+f"(d[3])
        : "r"(a[0]), "r"(a[1]), "r"(a[2]), "r"(a[3]), "r"(b0), "r"(b1));
}

// ---------------- NT fp16 GEMM (fp32 accum, ldmatrix fragments) ----------------
// C = scale * A @ B^T (+epilogue). A [M,lda], B [N,ldb] halves, K-major.
// Block tile 128x128, BK=64 halves, 8 warps (4x2), warp tile 32x64,
// 2-stage cp.async, 2 CTAs/SM, stride-72 smem (144B rows -> LDSM rows 4
// banks apart, conflict-free).
// EPI: 0 = +bias, ->half (QKV)   1 = exp, row-partial-sums, ->half (score)
//      2 = *invl[row], ->half (AV)   3 = +bias, ->float (final)
#define BK 64
#define STR 72
#define TILE_HALFS (128 * STR)               // 9216
#define STAGE_HALFS (2 * TILE_HALFS)         // 18432
#define SMEM_BYTES (2 * STAGE_HALFS * 2)     // 73728

template <int EPI>
__global__ void __launch_bounds__(256, 2) gemm_nt(
    const __half* __restrict__ A, const __half* __restrict__ B,
    const float* __restrict__ aux, void* __restrict__ Cv,
    int lda, int ldb, int ldc, int K,
    size_t sA, size_t sB, size_t sC, int sAux, float scale)
{
    extern __shared__ __half smem[];
    const uint32_t sbase = smem_u32(smem);

    const int tid  = threadIdx.x;
    const int lane = tid & 31;
    const int warp = tid >> 5;
    const int wr = (warp & 3) * 32;
    const int wc = (warp >> 2) * 64;

    const int b = blockIdx.z;
    A += (size_t)b * sA;
    B += (size_t)b * sB;
    if (aux) aux += (size_t)b * sAux;
    const int row0 = blockIdx.y * 128;
    const int col0 = blockIdx.x * 128;

    float acc[2][8][4];
    #pragma unroll
    for (int mi = 0; mi < 2; mi++)
        #pragma unroll
        for (int ni = 0; ni < 8; ni++)
            #pragma unroll
            for (int j = 0; j < 4; j++) acc[mi][ni][j] = 0.0f;

    const __half* gA = A + (size_t)row0 * lda;
    const __half* gB = B + (size_t)col0 * ldb;

    auto fill = [&](int t, int buf) {
        uint32_t smA = sbase + (uint32_t)buf * STAGE_HALFS * 2;
        uint32_t smB = smA + TILE_HALFS * 2;
        const __half* pa = gA + t * BK;
        const __half* pb = gB + t * BK;
        #pragma unroll
        for (int it = 0; it < 4; it++) {
            int idx = tid + it * 256;        // 0..1023
            int row = idx >> 3, cq = idx & 7;
            uint32_t off = 2u * (uint32_t)(row * STR + cq * 8);
            cp16(smA + off, pa + (size_t)row * lda + cq * 8);
            cp16(smB + off, pb + (size_t)row * ldb + cq * 8);
        }
    };

    const int ktiles = K / BK;
    fill(0, 0); CP_COMMIT();

    const int g = lane >> 2;
    const int q = lane & 3;
    const int l8 = lane & 7;
    const int jj = lane >> 3;    // which 8x8 matrix this lane addresses

    // ldmatrix per-lane byte offsets (kc=0), relative to tile base.
    // A matrices: j -> (row + 8*(j&1), k + 8*(j>>1))  => r0..r3 = a0..a3
    uint32_t aOff[2];
    #pragma unroll
    for (int mi = 0; mi < 2; mi++) {
        int row = wr + mi * 16 + (jj & 1) * 8 + l8;
        aOff[mi] = 2u * (uint32_t)(row * STR + (jj >> 1) * 8);
    }
    // B matrices: j -> (n + 8*(j>>1), k + 8*(j&1))  => (r0,r1)=b0,b1 of ni; (r2,r3)=ni+1
    uint32_t bOff[4];
    #pragma unroll
    for (int p = 0; p < 4; p++) {
        int n = wc + p * 16 + (jj >> 1) * 8 + l8;
        bOff[p] = 2u * (uint32_t)(n * STR + (jj & 1) * 8);
    }

    for (int t = 0; t < ktiles; t++) {
        CP_WAIT0();             // stage t resident
        __syncthreads();        // all warps done with t-1 -> buffer free
        if (t + 1 < ktiles) { fill(t + 1, (t + 1) & 1); CP_COMMIT(); }

        const uint32_t smA = sbase + (uint32_t)(t & 1) * STAGE_HALFS * 2;
        const uint32_t smB = smA + TILE_HALFS * 2;

        #pragma unroll
        for (int ks = 0; ks < 4; ks++) {      // 4 x k16
            const uint32_t kadd = (uint32_t)ks * 32;   // 16 halfs = 32B
            uint32_t a[2][4];
            #pragma unroll
            for (int mi = 0; mi < 2; mi++)
                LDSM4(a[mi][0], a[mi][1], a[mi][2], a[mi][3], smA + aOff[mi] + kadd);
            #pragma unroll
            for (int p = 0; p < 4; p++) {
                uint32_t b0, b1, b2, b3;
                LDSM4(b0, b1, b2, b3, smB + bOff[p] + kadd);
                #pragma unroll
                for (int mi = 0; mi < 2; mi++) {
                    mma_f16(acc[mi][2 * p],     a[mi], b0, b1);
                    mma_f16(acc[mi][2 * p + 1], a[mi], b2, b3);
                }
            }
        }
    }

    // Epilogue
    float rs0[2], rs1[2];
    #pragma unroll
    for (int mi = 0; mi < 2; mi++) { rs0[mi] = 0.0f; rs1[mi] = 0.0f; }

    #pragma unroll
    for (int mi = 0; mi < 2; mi++) {
        int rloc = wr + mi * 16 + g;
        int r = row0 + rloc;
        float il0 = 1.0f, il1 = 1.0f;
        if (EPI == 2) { il0 = aux[r]; il1 = aux[r + 8]; }
        #pragma unroll
        for (int ni = 0; ni < 8; ni++) {
            int c = wc + ni * 8 + 2 * q;
            float2 v0, v1;
            v0.x = acc[mi][ni][0] * scale;
            v0.y = acc[mi][ni][1] * scale;
            v1.x = acc[mi][ni][2] * scale;
            v1.y = acc[mi][ni][3] * scale;
            if (EPI == 0 || EPI == 3) {
                float bx = aux[col0 + c], by = aux[col0 + c + 1];
                v0.x += bx; v0.y += by;
                v1.x += bx; v1.y += by;
            }
            if (EPI == 1) {
                v0.x = fexp(v0.x); v0.y = fexp(v0.y);
                v1.x = fexp(v1.x); v1.y = fexp(v1.y);
                rs0[mi] += v0.x + v0.y;
                rs1[mi] += v1.x + v1.y;
            }
            if (EPI == 2) {
                v0.x *= il0; v0.y *= il0;
                v1.x *= il1; v1.y *= il1;
            }
            if (EPI == 3) {
                float* c0 = (float*)Cv + (size_t)b * sC + (size_t)r * ldc + col0;
                float* c1 = c0 + (size_t)8 * ldc;
                *reinterpret_cast<float2*>(c0 + c) = v0;
                *reinterpret_cast<float2*>(c1 + c) = v1;
            } else {
                __half* c0 = (__half*)Cv + (size_t)b * sC + (size_t)r * ldc + col0;
                __half* c1 = c0 + (size_t)8 * ldc;
                *reinterpret_cast<__half2*>(c0 + c) = __floats2half2_rn(v0.x, v0.y);
                *reinterpret_cast<__half2*>(c1 + c) = __floats2half2_rn(v1.x, v1.y);
            }
        }
    }

    if (EPI == 1) {
        // reduce partial row sums across q (4 lanes per row), write Lpart
        #pragma unroll
        for (int mi = 0; mi < 2; mi++) {
            rs0[mi] += __shfl_xor_sync(0xFFFFFFFF, rs0[mi], 1);
            rs0[mi] += __shfl_xor_sync(0xFFFFFFFF, rs0[mi], 2);
            rs1[mi] += __shfl_xor_sync(0xFFFFFFFF, rs1[mi], 1);
            rs1[mi] += __shfl_xor_sync(0xFFFFFFFF, rs1[mi], 2);
        }
        if (q == 0) {
            int slot = blockIdx.x * 2 + (warp >> 2);
            size_t base = (size_t)slot * TOK + (size_t)b * SEQ + row0 + wr;
            #pragma unroll
            for (int mi = 0; mi < 2; mi++) {
                g_Lpart[base + mi * 16 + g]     = rs0[mi];
                g_Lpart[base + mi * 16 + g + 8] = rs1[mi];
            }
        }
    }
}

// ---------------- row-sum finalize: invl[r] = 1 / sum_32 Lpart ----------------
__global__ void __launch_bounds__(256) rowsum_final(
    const float* __restrict__ LP, float* __restrict__ invl)
{
    int r = blockIdx.x * 256 + threadIdx.x;
    float s = 0.0f;
    #pragma unroll
    for (int i = 0; i < 32; i++) s += LP[(size_t)i * TOK + r];
    invl[r] = 1.0f / s;
}

// ---------------- fp32 -> fp16 copy ----------------
__global__ void __launch_bounds__(256) round_h(
    const float* __restrict__ in, __half* __restrict__ out)
{
    size_t i = ((size_t)blockIdx.x * 256 + threadIdx.x) * 8;
    float4 v0 = *reinterpret_cast<const float4*>(in + i);
    float4 v1 = *reinterpret_cast<const float4*>(in + i + 4);
    __half2 h[4];
    h[0] = __floats2half2_rn(v0.x, v0.y);
    h[1] = __floats2half2_rn(v0.z, v0.w);
    h[2] = __floats2half2_rn(v1.x, v1.y);
    h[3] = __floats2half2_rn(v1.z, v1.w);
    *reinterpret_cast<uint4*>(out + i) = *reinterpret_cast<uint4*>(h);
}

// ---------------- transposes ----------------
__global__ void __launch_bounds__(256) transpose_f2h(
    const float* __restrict__ in, __half* __restrict__ out,
    int ldIn, int ldOut)
{
    __shared__ float t[32][33];
    const int x = blockIdx.x * 32 + threadIdx.x;
    const int y0 = blockIdx.y * 32;
    #pragma unroll
    for (int j = threadIdx.y; j < 32; j += 8)
        t[j][threadIdx.x] = in[(size_t)(y0 + j) * ldIn + x];
    __syncthreads();
    const int ox = blockIdx.y * 32 + threadIdx.x;
    const int oy0 = blockIdx.x * 32;
    #pragma unroll
    for (int j = threadIdx.y; j < 32; j += 8)
        out[(size_t)(oy0 + j) * ldOut + ox] = __float2half_rn(t[threadIdx.x][j]);
}

__global__ void __launch_bounds__(256) transpose_h2h(
    const __half* __restrict__ in, __half* __restrict__ out,
    int ldIn, int ldOut, size_t sIn, size_t sOut)
{
    __shared__ __half t[32][34];
    in  += (size_t)blockIdx.z * sIn;
    out += (size_t)blockIdx.z * sOut;
    const int x = blockIdx.x * 32 + threadIdx.x;
    const int y0 = blockIdx.y * 32;
    #pragma unroll
    for (int j = threadIdx.y; j < 32; j += 8)
        t[j][threadIdx.x] = in[(size_t)(y0 + j) * ldIn + x];
    __syncthreads();
    const int ox = blockIdx.y * 32 + threadIdx.x;
    const int oy0 = blockIdx.x * 32;
    #pragma unroll
    for (int j = threadIdx.y; j < 32; j += 8)
        out[(size_t)(oy0 + j) * ldOut + ox] = t[threadIdx.x][j];
}

// ---------------- bias concat ----------------
__global__ void __launch_bounds__(256) concat_bias(
    const float* __restrict__ a, const float* __restrict__ b,
    const float* __restrict__ c, float* __restrict__ o)
{
    int i = blockIdx.x * 256 + threadIdx.x;   // 0..1535
    float v = (i < 512) ? a[i] : ((i < 1024) ? b[i - 512] : c[i - 1024]);
    o[i] = v;
}

// ---------------- host ----------------
extern "C" void kernel_launch(void* const* d_in, const int* in_sizes, int n_in,
                              void* d_out, int out_size)
{
    const float* x  = (const float*)d_in[0];
    const float* Wq = (const float*)d_in[1];
    const float* bq = (const float*)d_in[2];
    const float* Wk = (const float*)d_in[3];
    const float* bk = (const float*)d_in[4];
    const float* Wv = (const float*)d_in[5];
    const float* bv = (const float*)d_in[6];
    const float* Wo = (const float*)d_in[7];
    const float* bo = (const float*)d_in[8];
    float* out = (float*)d_out;

    __half *Xh, *QKV, *Vt, *S, *O, *WT;
    float *Bqkv, *LP, *L;
    cudaGetSymbolAddress((void**)&Xh,   g_Xh);
    cudaGetSymbolAddress((void**)&QKV,  g_QKV);
    cudaGetSymbolAddress((void**)&Vt,   g_Vt);
    cudaGetSymbolAddress((void**)&S,    g_S);
    cudaGetSymbolAddress((void**)&O,    g_O);
    cudaGetSymbolAddress((void**)&WT,   g_WT);
    cudaGetSymbolAddress((void**)&Bqkv, g_Bqkv);
    cudaGetSymbolAddress((void**)&LP,   g_Lpart);
    cudaGetSymbolAddress((void**)&L,    g_L);

    cudaFuncSetAttribute(gemm_nt<0>, cudaFuncAttributeMaxDynamicSharedMemorySize, SMEM_BYTES);
    cudaFuncSetAttribute(gemm_nt<1>, cudaFuncAttributeMaxDynamicSharedMemorySize, SMEM_BYTES);
    cudaFuncSetAttribute(gemm_nt<2>, cudaFuncAttributeMaxDynamicSharedMemorySize, SMEM_BYTES);
    cudaFuncSetAttribute(gemm_nt<3>, cudaFuncAttributeMaxDynamicSharedMemorySize, SMEM_BYTES);

    const float scale = 0.044194173824159216f;  // 1/sqrt(512)
    const size_t W2 = (size_t)EMB * EMB;

    // x -> fp16
    round_h<<<(TOK * EMB) / (256 * 8), 256>>>(x, Xh);

    // Weight transposes (fp32 -> fp16). WT rows 0..1535 = WqT|WkT|WvT, slot 3 = WoT.
    dim3 tb(32, 8);
    dim3 tgW(EMB / 32, EMB / 32, 1);
    transpose_f2h<<<tgW, tb>>>(Wq, WT + 0 * W2, EMB, EMB);
    transpose_f2h<<<tgW, tb>>>(Wk, WT + 1 * W2, EMB, EMB);
    transpose_f2h<<<tgW, tb>>>(Wv, WT + 2 * W2, EMB, EMB);
    transpose_f2h<<<tgW, tb>>>(Wo, WT + 3 * W2, EMB, EMB);
    concat_bias<<<6, 256>>>(bq, bk, bv, Bqkv);

    // Fused QKV projection: QKV[16384,1536] = Xh @ [Wq|Wk|Wv] + b -> fp16
    dim3 gqkv(3 * EMB / 128, TOK / 128, 1);
    gemm_nt<0><<<gqkv, 256, SMEM_BYTES>>>(
        Xh, WT, Bqkv, QKV, EMB, EMB, 3 * EMB, EMB, 0, 0, 0, 0, 1.0f);

    // V^T per batch: [EMB, SEQ] (V = QKV cols 1024..1535)
    dim3 tgV(EMB / 32, SEQ / 32, BATCH);
    transpose_h2h<<<tgV, tb>>>(QKV + 2 * EMB, Vt, 3 * EMB, SEQ,
                               (size_t)SEQ * 3 * EMB, (size_t)SEQ * EMB);

    // Scores + fused exp + row partial sums: S = exp(scale * Q @ K^T) -> fp16
    dim3 gscore(SEQ / 128, SEQ / 128, BATCH);
    gemm_nt<1><<<gscore, 256, SMEM_BYTES>>>(
        QKV, QKV + EMB, nullptr, S, 3 * EMB, 3 * EMB, SEQ, EMB,
        (size_t)SEQ * 3 * EMB, (size_t)SEQ * 3 * EMB, (size_t)SEQ * SEQ, 0, scale);

    // invl[r] = 1 / sum(exp row)
    rowsum_final<<<TOK / 256, 256>>>(LP, L);

    // O[b] = (S[b] @ V[b]) * invl[row] -> fp16
    dim3 gav(EMB / 128, SEQ / 128, BATCH);
    gemm_nt<2><<<gav, 256, SMEM_BYTES>>>(
        S, Vt, L, O, SEQ, SEQ, EMB, SEQ,
        (size_t)SEQ * SEQ, (size_t)SEQ * EMB, (size_t)SEQ * EMB, SEQ, 1.0f);

    // Final projection: out = O @ Wo + bo (fp32 out)
    dim3 gout(EMB / 128, TOK / 128, 1);
    gemm_nt<3><<<gout, 256, SMEM_BYTES>>>(
        O, WT + 3 * W2, bo, out, EMB, EMB, EMB, EMB, 0, 0, 0, 0, 1.0f);
}

// round 11
// speedup vs baseline: 1.9997x; 1.0090x over previous
#include <cuda_runtime.h>
#include <cuda_fp16.h>
#include <cstdint>

#define EMB 512
#define BATCH 8
#define SEQ 2048
#define TOK (BATCH * SEQ)   // 16384

// Scratch (allocation-free rule: __device__ globals)
__device__ __half g_Xh[(size_t)TOK * EMB];
__device__ __half g_QKV[(size_t)TOK * 3 * EMB];
__device__ __half g_Vt[(size_t)TOK * EMB];
__device__ __half g_O[(size_t)TOK * EMB];
__device__ __half g_S[(size_t)BATCH * SEQ * SEQ];
__device__ __half g_WT[4 * EMB * EMB];
__device__ float  g_Bqkv[3 * EMB];
__device__ float  g_Lpart[32 * TOK];
__device__ float  g_L[TOK];

// ---------------- PTX helpers (compute_103-safe) ----------------
__device__ __forceinline__ uint32_t smem_u32(const void* p) {
    uint32_t a;
    asm("{ .reg .u64 t; cvta.to.shared.u64 t, %1; cvt.u32.u64 %0, t; }" : "=r"(a) : "l"(p));
    return a;
}
__device__ __forceinline__ void cp16(uint32_t s, const void* g) {
    asm volatile("cp.async.cg.shared.global [%0], [%1], 16;" :: "r"(s), "l"(g));
}
#define CP_COMMIT() asm volatile("cp.async.commit_group;" ::: "memory")
#define CP_WAIT0()  asm volatile("cp.async.wait_group 0;" ::: "memory")

#define LDSM4(r0, r1, r2, r3, addr)                                            \
    asm volatile("ldmatrix.sync.aligned.m8n8.x4.shared.b16 {%0,%1,%2,%3}, [%4];" \
        : "=r"(r0), "=r"(r1), "=r"(r2), "=r"(r3) : "r"(addr))

// FMA-pipe exp (no MUFU): x ~ [-16,16], rel err ~2e-6.
__device__ __forceinline__ float fexp(float x) {
    float t = x * 1.4426950408889634f;
    float r = rintf(t);
    float f = t - r;
    float p =          1.3333558146428443e-3f;
    p = fmaf(p, f,     9.6181291076284772e-3f);
    p = fmaf(p, f,     5.5504108664821580e-2f);
    p = fmaf(p, f,     2.4022650695910071e-1f);
    p = fmaf(p, f,     6.9314718055994531e-1f);
    p = fmaf(p, f,     1.0f);
    int i = (int)r;
    return p * __int_as_float((i + 127) << 23);
}

// fp16 MMA m16n8k16, fp32 accumulate.
__device__ __forceinline__ void mma_f16(float* d, const uint32_t* a, uint32_t b0, uint32_t b1) {
    asm volatile(
        "mma.sync.aligned.m16n8k16.row.col.f32.f16.f16.f32 "
        "{%0,%1,%2,%3}, {%4,%5,%6,%7}, {%8,%9}, {%0,%1,%2,%3};"
        : "+f"(d[0]), "+f"(d[1]), "+f"(d[2]), "+f"(d[3])
        : "r"(a[0]), "r"(a[1]), "r"(a[2]), "r"(a[3]), "r"(b0), "r"(b1));
}

// ---------------- NT fp16 GEMM (fp32 accum, ldmatrix, 64x64 warp tiles) -----
// C = scale * A @ B^T (+epilogue). A [M,lda], B [N,ldb] halves, K-major.
// Block tile 128x128, BK=64 halves, 4 warps (2x2), warp tile 64x64 —
// halves smem crossbar read traffic vs 32x64 tiles. 2-stage cp.async,
// 2 CTAs/SM, stride-72 smem (144B rows -> conflict-free LDSM).
// EPI: 0 = +bias, ->half (QKV)   1 = exp, row-partial-sums, ->half (score)
//      2 = *invl[row], ->half (AV)   3 = +bias, ->float (final)
#define BK 64
#define STR 72
#define TILE_HALFS (128 * STR)               // 9216
#define STAGE_HALFS (2 * TILE_HALFS)         // 18432
#define SMEM_BYTES (2 * STAGE_HALFS * 2)     // 73728

template <int EPI>
__global__ void __launch_bounds__(128, 2) gemm_nt(
    const __half* __restrict__ A, const __half* __restrict__ B,
    const float* __restrict__ aux, void* __restrict__ Cv,
    int lda, int ldb, int ldc, int K,
    size_t sA, size_t sB, size_t sC, int sAux, float scale)
{
    extern __shared__ __half smem[];
    const uint32_t sbase = smem_u32(smem);

    const int tid  = threadIdx.x;
    const int lane = tid & 31;
    const int warp = tid >> 5;
    const int wr = (warp & 1) * 64;   // warp row offset (2 row-warps)
    const int wc = (warp >> 1) * 64;  // warp col offset (2 col-warps)

    const int b = blockIdx.z;
    A += (size_t)b * sA;
    B += (size_t)b * sB;
    if (aux) aux += (size_t)b * sAux;
    const int row0 = blockIdx.y * 128;
    const int col0 = blockIdx.x * 128;

    float acc[4][8][4];
    #pragma unroll
    for (int mi = 0; mi < 4; mi++)
        #pragma unroll
        for (int ni = 0; ni < 8; ni++)
            #pragma unroll
            for (int j = 0; j < 4; j++) acc[mi][ni][j] = 0.0f;

    const __half* gA = A + (size_t)row0 * lda;
    const __half* gB = B + (size_t)col0 * ldb;

    auto fill = [&](int t, int buf) {
        uint32_t smA = sbase + (uint32_t)buf * STAGE_HALFS * 2;
        uint32_t smB = smA + TILE_HALFS * 2;
        const __half* pa = gA + t * BK;
        const __half* pb = gB + t * BK;
        const int frow0 = tid >> 3;      // 0..15
        const int cq    = tid & 7;       // 16B chunk in 128B row
        int row = frow0;
        #pragma unroll
        for (int it = 0; it < 8; it++, row += 16) {
            uint32_t off = 2u * (uint32_t)(row * STR + cq * 8);
            cp16(smA + off, pa + (size_t)row * lda + cq * 8);
            cp16(smB + off, pb + (size_t)row * ldb + cq * 8);
        }
    };

    const int ktiles = K / BK;
    fill(0, 0); CP_COMMIT();

    const int g = lane >> 2;
    const int q = lane & 3;
    const int l8 = lane & 7;
    const int jj = lane >> 3;    // which 8x8 matrix this lane addresses

    // ldmatrix per-lane byte offsets (kc=0), relative to tile base.
    // A matrices: j -> (row + 8*(j&1), k + 8*(j>>1))  => r0..r3 = a0..a3
    uint32_t aOff[4];
    #pragma unroll
    for (int mi = 0; mi < 4; mi++) {
        int row = wr + mi * 16 + (jj & 1) * 8 + l8;
        aOff[mi] = 2u * (uint32_t)(row * STR + (jj >> 1) * 8);
    }
    // B matrices: j -> (n + 8*(j>>1), k + 8*(j&1))  => (r0,r1)=b of ni; (r2,r3)=ni+1
    uint32_t bOff[4];
    #pragma unroll
    for (int p = 0; p < 4; p++) {
        int n = wc + p * 16 + (jj >> 1) * 8 + l8;
        bOff[p] = 2u * (uint32_t)(n * STR + (jj & 1) * 8);
    }

    for (int t = 0; t < ktiles; t++) {
        CP_WAIT0();             // stage t resident
        __syncthreads();        // all warps done with t-1 -> buffer free
        if (t + 1 < ktiles) { fill(t + 1, (t + 1) & 1); CP_COMMIT(); }

        const uint32_t smA = sbase + (uint32_t)(t & 1) * STAGE_HALFS * 2;
        const uint32_t smB = smA + TILE_HALFS * 2;

        #pragma unroll
        for (int ks = 0; ks < 4; ks++) {      // 4 x k16
            const uint32_t kadd = (uint32_t)ks * 32;   // 16 halfs = 32B
            uint32_t a[4][4];
            #pragma unroll
            for (int mi = 0; mi < 4; mi++)
                LDSM4(a[mi][0], a[mi][1], a[mi][2], a[mi][3], smA + aOff[mi] + kadd);
            #pragma unroll
            for (int p = 0; p < 4; p++) {
                uint32_t b0, b1, b2, b3;
                LDSM4(b0, b1, b2, b3, smB + bOff[p] + kadd);
                #pragma unroll
                for (int mi = 0; mi < 4; mi++) {
                    mma_f16(acc[mi][2 * p],     a[mi], b0, b1);
                    mma_f16(acc[mi][2 * p + 1], a[mi], b2, b3);
                }
            }
        }
    }

    // Epilogue
    float rs0[4], rs1[4];
    #pragma unroll
    for (int mi = 0; mi < 4; mi++) { rs0[mi] = 0.0f; rs1[mi] = 0.0f; }

    #pragma unroll
    for (int mi = 0; mi < 4; mi++) {
        int rloc = wr + mi * 16 + g;
        int r = row0 + rloc;
        float il0 = 1.0f, il1 = 1.0f;
        if (EPI == 2) { il0 = aux[r]; il1 = aux[r + 8]; }
        #pragma unroll
        for (int ni = 0; ni < 8; ni++) {
            int c = wc + ni * 8 + 2 * q;
            float2 v0, v1;
            v0.x = acc[mi][ni][0] * scale;
            v0.y = acc[mi][ni][1] * scale;
            v1.x = acc[mi][ni][2] * scale;
            v1.y = acc[mi][ni][3] * scale;
            if (EPI == 0 || EPI == 3) {
                float bx = aux[col0 + c], by = aux[col0 + c + 1];
                v0.x += bx; v0.y += by;
                v1.x += bx; v1.y += by;
            }
            if (EPI == 1) {
                v0.x = fexp(v0.x); v0.y = fexp(v0.y);
                v1.x = fexp(v1.x); v1.y = fexp(v1.y);
                rs0[mi] += v0.x + v0.y;
                rs1[mi] += v1.x + v1.y;
            }
            if (EPI == 2) {
                v0.x *= il0; v0.y *= il0;
                v1.x *= il1; v1.y *= il1;
            }
            if (EPI == 3) {
                float* c0 = (float*)Cv + (size_t)b * sC + (size_t)r * ldc + col0;
                float* c1 = c0 + (size_t)8 * ldc;
                *reinterpret_cast<float2*>(c0 + c) = v0;
                *reinterpret_cast<float2*>(c1 + c) = v1;
            } else {
                __half* c0 = (__half*)Cv + (size_t)b * sC + (size_t)r * ldc + col0;
                __half* c1 = c0 + (size_t)8 * ldc;
                *reinterpret_cast<__half2*>(c0 + c) = __floats2half2_rn(v0.x, v0.y);
                *reinterpret_cast<__half2*>(c1 + c) = __floats2half2_rn(v1.x, v1.y);
            }
        }
    }

    if (EPI == 1) {
        // reduce partial row sums across q (4 lanes per row), write Lpart.
        // 2 col-warps hold different column halves -> 2 slots per blockIdx.x.
        #pragma unroll
        for (int mi = 0; mi < 4; mi++) {
            rs0[mi] += __shfl_xor_sync(0xFFFFFFFF, rs0[mi], 1);
            rs0[mi] += __shfl_xor_sync(0xFFFFFFFF, rs0[mi], 2);
            rs1[mi] += __shfl_xor_sync(0xFFFFFFFF, rs1[mi], 1);
            rs1[mi] += __shfl_xor_sync(0xFFFFFFFF, rs1[mi], 2);
        }
        if (q == 0) {
            int slot = blockIdx.x * 2 + (warp >> 1);
            size_t base = (size_t)slot * TOK + (size_t)b * SEQ + row0 + wr;
            #pragma unroll
            for (int mi = 0; mi < 4; mi++) {
                g_Lpart[base + mi * 16 + g]     = rs0[mi];
                g_Lpart[base + mi * 16 + g + 8] = rs1[mi];
            }
        }
    }
}

// ---------------- row-sum finalize: invl[r] = 1 / sum_32 Lpart ----------------
__global__ void __launch_bounds__(256) rowsum_final(
    const float* __restrict__ LP, float* __restrict__ invl)
{
    int r = blockIdx.x * 256 + threadIdx.x;
    float s = 0.0f;
    #pragma unroll
    for (int i = 0; i < 32; i++) s += LP[(size_t)i * TOK + r];
    invl[r] = 1.0f / s;
}

// ---------------- fp32 -> fp16 copy ----------------
__global__ void __launch_bounds__(256) round_h(
    const float* __restrict__ in, __half* __restrict__ out)
{
    size_t i = ((size_t)blockIdx.x * 256 + threadIdx.x) * 8;
    float4 v0 = *reinterpret_cast<const float4*>(in + i);
    float4 v1 = *reinterpret_cast<const float4*>(in + i + 4);
    __half2 h[4];
    h[0] = __floats2half2_rn(v0.x, v0.y);
    h[1] = __floats2half2_rn(v0.z, v0.w);
    h[2] = __floats2half2_rn(v1.x, v1.y);
    h[3] = __floats2half2_rn(v1.z, v1.w);
    *reinterpret_cast<uint4*>(out + i) = *reinterpret_cast<uint4*>(h);
}

// ---------------- batched 512x512 weight transpose (fp32 -> fp16) ----------
__global__ void __launch_bounds__(256) transpose_w4(
    const float* __restrict__ w0, const float* __restrict__ w1,
    const float* __restrict__ w2, const float* __restrict__ w3,
    __half* __restrict__ out)
{
    __shared__ float t[32][33];
    const float* in = (blockIdx.z == 0) ? w0 : (blockIdx.z == 1) ? w1
                     : (blockIdx.z == 2) ? w2 : w3;
    out += (size_t)blockIdx.z * EMB * EMB;
    const int x = blockIdx.x * 32 + threadIdx.x;
    const int y0 = blockIdx.y * 32;
    #pragma unroll
    for (int j = threadIdx.y; j < 32; j += 8)
        t[j][threadIdx.x] = in[(size_t)(y0 + j) * EMB + x];
    __syncthreads();
    const int ox = blockIdx.y * 32 + threadIdx.x;
    const int oy0 = blockIdx.x * 32;
    #pragma unroll
    for (int j = threadIdx.y; j < 32; j += 8)
        out[(size_t)(oy0 + j) * EMB + ox] = __float2half_rn(t[threadIdx.x][j]);
}

__global__ void __launch_bounds__(256) transpose_h2h(
    const __half* __restrict__ in, __half* __restrict__ out,
    int ldIn, int ldOut, size_t sIn, size_t sOut)
{
    __shared__ __half t[32][34];
    in  += (size_t)blockIdx.z * sIn;
    out += (size_t)blockIdx.z * sOut;
    const int x = blockIdx.x * 32 + threadIdx.x;
    const int y0 = blockIdx.y * 32;
    #pragma unroll
    for (int j = threadIdx.y; j < 32; j += 8)
        t[j][threadIdx.x] = in[(size_t)(y0 + j) * ldIn + x];
    __syncthreads();
    const int ox = blockIdx.y * 32 + threadIdx.x;
    const int oy0 = blockIdx.x * 32;
    #pragma unroll
    for (int j = threadIdx.y; j < 32; j += 8)
        out[(size_t)(oy0 + j) * ldOut + ox] = t[threadIdx.x][j];
}

// ---------------- bias concat ----------------
__global__ void __launch_bounds__(256) concat_bias(
    const float* __restrict__ a, const float* __restrict__ b,
    const float* __restrict__ c, float* __restrict__ o)
{
    int i = blockIdx.x * 256 + threadIdx.x;   // 0..1535
    float v = (i < 512) ? a[i] : ((i < 1024) ? b[i - 512] : c[i - 1024]);
    o[i] = v;
}

// ---------------- host ----------------
extern "C" void kernel_launch(void* const* d_in, const int* in_sizes, int n_in,
                              void* d_out, int out_size)
{
    const float* x  = (const float*)d_in[0];
    const float* Wq = (const float*)d_in[1];
    const float* bq = (const float*)d_in[2];
    const float* Wk = (const float*)d_in[3];
    const float* bk = (const float*)d_in[4];
    const float* Wv = (const float*)d_in[5];
    const float* bv = (const float*)d_in[6];
    const float* Wo = (const float*)d_in[7];
    const float* bo = (const float*)d_in[8];
    float* out = (float*)d_out;

    __half *Xh, *QKV, *Vt, *S, *O, *WT;
    float *Bqkv, *LP, *L;
    cudaGetSymbolAddress((void**)&Xh,   g_Xh);
    cudaGetSymbolAddress((void**)&QKV,  g_QKV);
    cudaGetSymbolAddress((void**)&Vt,   g_Vt);
    cudaGetSymbolAddress((void**)&S,    g_S);
    cudaGetSymbolAddress((void**)&O,    g_O);
    cudaGetSymbolAddress((void**)&WT,   g_WT);
    cudaGetSymbolAddress((void**)&Bqkv, g_Bqkv);
    cudaGetSymbolAddress((void**)&LP,   g_Lpart);
    cudaGetSymbolAddress((void**)&L,    g_L);

    cudaFuncSetAttribute(gemm_nt<0>, cudaFuncAttributeMaxDynamicSharedMemorySize, SMEM_BYTES);
    cudaFuncSetAttribute(gemm_nt<1>, cudaFuncAttributeMaxDynamicSharedMemorySize, SMEM_BYTES);
    cudaFuncSetAttribute(gemm_nt<2>, cudaFuncAttributeMaxDynamicSharedMemorySize, SMEM_BYTES);
    cudaFuncSetAttribute(gemm_nt<3>, cudaFuncAttributeMaxDynamicSharedMemorySize, SMEM_BYTES);

    const float scale = 0.044194173824159216f;  // 1/sqrt(512)
    const size_t W2 = (size_t)EMB * EMB;

    // x -> fp16
    round_h<<<(TOK * EMB) / (256 * 8), 256>>>(x, Xh);

    // All 4 weight transposes in ONE launch (fp32 -> fp16).
    // WT slots: 0=WqT 1=WkT 2=WvT 3=WoT; slots 0..2 contiguous = [Wq|Wk|Wv]^T.
    dim3 tb(32, 8);
    dim3 tgW4(EMB / 32, EMB / 32, 4);
    transpose_w4<<<tgW4, tb>>>(Wq, Wk, Wv, Wo, WT);
    concat_bias<<<6, 256>>>(bq, bk, bv, Bqkv);

    // Fused QKV projection: QKV[16384,1536] = Xh @ [Wq|Wk|Wv] + b -> fp16
    dim3 gqkv(3 * EMB / 128, TOK / 128, 1);
    gemm_nt<0><<<gqkv, 128, SMEM_BYTES>>>(
        Xh, WT, Bqkv, QKV, EMB, EMB, 3 * EMB, EMB, 0, 0, 0, 0, 1.0f);

    // V^T per batch: [EMB, SEQ] (V = QKV cols 1024..1535)
    dim3 tgV(EMB / 32, SEQ / 32, BATCH);
    transpose_h2h<<<tgV, tb>>>(QKV + 2 * EMB, Vt, 3 * EMB, SEQ,
                               (size_t)SEQ * 3 * EMB, (size_t)SEQ * EMB);

    // Scores + fused exp + row partial sums: S = exp(scale * Q @ K^T) -> fp16
    dim3 gscore(SEQ / 128, SEQ / 128, BATCH);
    gemm_nt<1><<<gscore, 128, SMEM_BYTES>>>(
        QKV, QKV + EMB, nullptr, S, 3 * EMB, 3 * EMB, SEQ, EMB,
        (size_t)SEQ * 3 * EMB, (size_t)SEQ * 3 * EMB, (size_t)SEQ * SEQ, 0, scale);

    // invl[r] = 1 / sum(exp row)
    rowsum_final<<<TOK / 256, 256>>>(LP, L);

    // O[b] = (S[b] @ V[b]) * invl[row] -> fp16
    dim3 gav(EMB / 128, SEQ / 128, BATCH);
    gemm_nt<2><<<gav, 128, SMEM_BYTES>>>(
        S, Vt, L, O, SEQ, SEQ, EMB, SEQ,
        (size_t)SEQ * SEQ, (size_t)SEQ * EMB, (size_t)SEQ * EMB, SEQ, 1.0f);

    // Final projection: out = O @ Wo + bo (fp32 out)
    dim3 gout(EMB / 128, TOK / 128, 1);
    gemm_nt<3><<<gout, 128, SMEM_BYTES>>>(
        O, WT + 3 * W2, bo, out, EMB, EMB, EMB, EMB, 0, 0, 0, 0, 1.0f);
}